// round 2
// baseline (speedup 1.0000x reference)
#include <cuda_runtime.h>
#include <math.h>

#define Bx   32
#define Sx   256
#define EMBD 300
#define HIDD 300
#define NTAG 9
#define GATES 1200          // 4*HIDD
#define NCOL  2400          // both directions

// ---------------- scratch (static device globals; no allocs) ----------------
__device__ float g_E [Bx*Sx*EMBD];            // (S,B,300) gathered embeddings
__device__ float g_gx[19660800];              // (S,B,2400) input-transform + biases
__device__ float g_H [4915200];               // (S,B,600) hidden states (fwd|bwd)
__device__ float g_sc[Bx*Sx];                 // CRF numerator terms
__device__ int   g_ctr[8];                    // recurrence sync counters

__device__ __forceinline__ float sigm(float x){ return 1.f/(1.f+expf(-x)); }

// ---------------- K0: embedding gather + counter reset ----------------
__global__ void k_embed(const int* __restrict__ x, const float* __restrict__ emb){
    if (blockIdx.x==0 && threadIdx.x<8) g_ctr[threadIdx.x]=0;
    int idx = blockIdx.x*blockDim.x + threadIdx.x;
    if (idx < Bx*Sx*EMBD){
        int r = idx/EMBD, k = idx - r*EMBD;
        int s = r/Bx, b = r - s*Bx;
        int tok = __ldg(&x[b*Sx + s]);
        g_E[idx] = __ldg(&emb[(size_t)tok*EMBD + k]);
    }
}

// ---------------- K1: gx GEMM (8192 x 2400 x 300), fp32 tiled ----------------
__device__ __forceinline__ float wrow(const float* wf, const float* wb, int gn, int k){
    return (gn < GATES) ? __ldg(&wf[gn*EMBD + k]) : __ldg(&wb[(gn-GATES)*EMBD + k]);
}

__global__ void __launch_bounds__(256) k_gx(
        const float* __restrict__ wf, const float* __restrict__ wb,
        const float* __restrict__ bif, const float* __restrict__ bhf,
        const float* __restrict__ bib, const float* __restrict__ bhb){
    __shared__ float As[8][132];
    __shared__ float Bs[8][128];
    int t  = threadIdx.x;
    int m0 = blockIdx.x*128;
    int n0 = blockIdx.y*128;
    int tx = t & 15, ty = t >> 4;

    float acc[8][8];
    #pragma unroll
    for (int i=0;i<8;i++)
        #pragma unroll
        for (int j=0;j<8;j++) acc[i][j]=0.f;

    int arow = t>>1, ahalf = t&1;
    float4 aR; float bR[4];
    {   // prefetch chunk 0
        int k = ahalf*4;
        aR = *(const float4*)(g_E + (size_t)(m0+arow)*EMBD + k);
        #pragma unroll
        for (int p=0;p<4;p++){ int i=t+p*256; int n=i>>3; int kk=i&7;
            int gn=n0+n; bR[p] = (gn<NCOL) ? wrow(wf,wb,gn,kk) : 0.f; }
    }
    for (int ck=0; ck<38; ck++){
        __syncthreads();
        {   float av[4]={aR.x,aR.y,aR.z,aR.w};
            #pragma unroll
            for (int i=0;i<4;i++) As[ahalf*4+i][arow]=av[i];
            #pragma unroll
            for (int p=0;p<4;p++){ int i=t+p*256; Bs[i&7][i>>3]=bR[p]; }
        }
        __syncthreads();
        if (ck < 37){
            int k0=(ck+1)*8;
            int k = k0 + ahalf*4;
            aR = (k<EMBD) ? *(const float4*)(g_E + (size_t)(m0+arow)*EMBD + k)
                          : make_float4(0.f,0.f,0.f,0.f);
            #pragma unroll
            for (int p=0;p<4;p++){ int i=t+p*256; int n=i>>3; int kk=k0+(i&7);
                int gn=n0+n; bR[p] = (gn<NCOL && kk<EMBD) ? wrow(wf,wb,gn,kk) : 0.f; }
        }
        #pragma unroll
        for (int kk=0;kk<8;kk++){
            float4 a0=*(const float4*)&As[kk][ty*8];
            float4 a1=*(const float4*)&As[kk][ty*8+4];
            float4 b0=*(const float4*)&Bs[kk][tx*8];
            float4 b1=*(const float4*)&Bs[kk][tx*8+4];
            float av[8]={a0.x,a0.y,a0.z,a0.w,a1.x,a1.y,a1.z,a1.w};
            float bv[8]={b0.x,b0.y,b0.z,b0.w,b1.x,b1.y,b1.z,b1.w};
            #pragma unroll
            for (int i=0;i<8;i++)
                #pragma unroll
                for (int j=0;j<8;j++)
                    acc[i][j]=fmaf(av[i],bv[j],acc[i][j]);
        }
    }
    #pragma unroll
    for (int i=0;i<8;i++){
        int gm = m0 + ty*8 + i;
        #pragma unroll
        for (int j0=0;j0<8;j0+=4){
            int gn = n0 + tx*8 + j0;
            if (gn < NCOL){
                float vv[4];
                #pragma unroll
                for (int j=0;j<4;j++){
                    int c=gn+j;
                    float bias = (c<GATES)? bif[c]+bhf[c] : bib[c-GATES]+bhb[c-GATES];
                    vv[j]=acc[i][j0+j]+bias;
                }
                *(float4*)(g_gx + (size_t)gm*NCOL + gn) =
                    make_float4(vv[0],vv[1],vv[2],vv[3]);
            }
        }
    }
}

// ---------------- K2: persistent bidirectional LSTM recurrence ----------------
#define HS 15          // hidden units per block
#define NHS 20         // hidden slices (20*15=300)
#define NBS 3          // batch slices (11,11,10)
#define NG 60          // 4*HS gate rows per block
#define BMAX 12        // padded per-block batch
#define KSPLIT 5       // k-dim split (5*60=300)
#define RECUR_SMEM ((NG*300 + BMAX*300 + KSPLIT*NG*BMAX + NG*BMAX + HS*BMAX)*4)

__device__ __forceinline__ void fma4(float& a, float4 w, float4 h){
    a=fmaf(w.x,h.x,a); a=fmaf(w.y,h.y,a); a=fmaf(w.z,h.z,a); a=fmaf(w.w,h.w,a);
}

__global__ void __launch_bounds__(256,1) k_recur(
        const float* __restrict__ whhf, const float* __restrict__ whhb){
    extern __shared__ float smdyn[];
    float* Ws   = smdyn;                       // [NG][300]
    float* Hs   = Ws   + NG*300;               // [BMAX][300]
    float* Part = Hs   + BMAX*300;             // [KSPLIT][NG][BMAX]
    float* Gsum = Part + KSPLIT*NG*BMAX;       // [NG][BMAX]
    float* Cs   = Gsum + NG*BMAX;              // [HS][BMAX]

    int bx  = blockIdx.x;
    int dir = bx / (NHS*NBS);
    int r   = bx % (NHS*NBS);
    int hs  = r / NBS;
    int bs  = r % NBS;
    int bch = (bs<2)?11:10;
    int b0g = bs*11;
    int j0  = hs*HS;
    const float* whh = dir ? whhb : whhf;
    int t = threadIdx.x;

    for (int i=t;i<NG*300;i+=256){
        int row=i/300, k=i-row*300;
        int type=row/HS, jj=row-type*HS;
        Ws[i]=whh[(size_t)(type*HIDD + j0 + jj)*HIDD + k];
    }
    for (int i=t;i<BMAX*300;i+=256) Hs[i]=0.f;
    for (int i=t;i<HS*BMAX;i+=256)  Cs[i]=0.f;
    __syncthreads();

    bool comp=(t<225);
    int kp=0, gt=0, bt=0;
    if (comp){ kp=t/45; int rem=t%45; gt=rem/3; bt=rem%3; }
    volatile int* vc = (volatile int*)(g_ctr + dir*NBS + bs);

    for (int step=0; step<Sx; step++){
        int s = dir ? (Sx-1-step) : step;
        if (step>0){
            int sprev = dir ? s+1 : s-1;
            if (t==0){ int target=NHS*step; while (*vc < target) { } }
            __syncthreads();
            __threadfence();
            for (int i=t;i<bch*300;i+=256){
                int b=i/300, k=i-b*300;
                Hs[b*300+k]=g_H[((size_t)(sprev*Bx + b0g + b))*(2*HIDD) + dir*HIDD + k];
            }
            __syncthreads();
        }
        if (comp){
            float acc[4][4];
            #pragma unroll
            for (int i=0;i<4;i++)
                #pragma unroll
                for (int j=0;j<4;j++) acc[i][j]=0.f;
            const float* wr = Ws + (gt*4)*300 + kp*60;
            const float* hr = Hs + (bt*4)*300 + kp*60;
            #pragma unroll
            for (int c=0;c<15;c++){
                int k=c*4;
                float4 w0=*(const float4*)(wr      +k);
                float4 w1=*(const float4*)(wr+300  +k);
                float4 w2=*(const float4*)(wr+600  +k);
                float4 w3=*(const float4*)(wr+900  +k);
                float4 h0=*(const float4*)(hr      +k);
                float4 h1=*(const float4*)(hr+300  +k);
                float4 h2=*(const float4*)(hr+600  +k);
                float4 h3=*(const float4*)(hr+900  +k);
                fma4(acc[0][0],w0,h0); fma4(acc[0][1],w0,h1); fma4(acc[0][2],w0,h2); fma4(acc[0][3],w0,h3);
                fma4(acc[1][0],w1,h0); fma4(acc[1][1],w1,h1); fma4(acc[1][2],w1,h2); fma4(acc[1][3],w1,h3);
                fma4(acc[2][0],w2,h0); fma4(acc[2][1],w2,h1); fma4(acc[2][2],w2,h2); fma4(acc[2][3],w2,h3);
                fma4(acc[3][0],w3,h0); fma4(acc[3][1],w3,h1); fma4(acc[3][2],w3,h2); fma4(acc[3][3],w3,h3);
            }
            #pragma unroll
            for (int i=0;i<4;i++)
                #pragma unroll
                for (int j=0;j<4;j++)
                    Part[(kp*NG + gt*4+i)*BMAX + bt*4+j]=acc[i][j];
        }
        __syncthreads();
        for (int i=t;i<NG*BMAX;i+=256){
            Gsum[i]=Part[i]+Part[NG*BMAX+i]+Part[2*NG*BMAX+i]
                   +Part[3*NG*BMAX+i]+Part[4*NG*BMAX+i];
        }
        __syncthreads();
        int ncell=HS*bch;
        for (int cell=t; cell<ncell; cell+=256){
            int b=cell/HS, jj=cell-b*HS;
            float gi=Gsum[(0*HS+jj)*BMAX+b];
            float gf=Gsum[(1*HS+jj)*BMAX+b];
            float gg=Gsum[(2*HS+jj)*BMAX+b];
            float go=Gsum[(3*HS+jj)*BMAX+b];
            const float* gp=g_gx + ((size_t)(s*Bx + b0g + b))*NCOL + dir*GATES + (j0+jj);
            gi+=gp[0]; gf+=gp[HIDD]; gg+=gp[2*HIDD]; go+=gp[3*HIDD];
            float co=Cs[jj*BMAX+b];
            float cn=sigm(gf)*co + sigm(gi)*tanhf(gg);
            float hn=sigm(go)*tanhf(cn);
            Cs[jj*BMAX+b]=cn;
            g_H[((size_t)(s*Bx + b0g + b))*(2*HIDD) + dir*HIDD + j0 + jj]=hn;
        }
        __threadfence();
        __syncthreads();
        if (t==0) atomicAdd(g_ctr + dir*NBS + bs, 1);
    }
}

// ---------------- K3a: logits + softmax + CRF numerator terms ----------------
__global__ void __launch_bounds__(288) k_head(
        const float* __restrict__ linw, const float* __restrict__ linb,
        const int* __restrict__ y, const float* __restrict__ start_t,
        const float* __restrict__ end_t, const float* __restrict__ trans,
        float* __restrict__ out){
    __shared__ float sh[2*HIDD];
    __shared__ float lg[NTAG];
    int bxid=blockIdx.x;
    int b=bxid/Sx, s=bxid%Sx;
    int t=threadIdx.x;
    const float* hrow=g_H + (size_t)(s*Bx+b)*(2*HIDD);
    for (int k=t;k<2*HIDD;k+=288) sh[k]=hrow[k];
    __syncthreads();
    int w=t>>5, lane=t&31;
    float acc=0.f;
    for (int k=lane;k<2*HIDD;k+=32) acc=fmaf(sh[k],__ldg(&linw[w*(2*HIDD)+k]),acc);
    #pragma unroll
    for (int off=16;off;off>>=1) acc += __shfl_down_sync(0xffffffffu,acc,off);
    if (lane==0) lg[w]=acc+__ldg(&linb[w]);
    __syncthreads();
    if (t==0){
        float m=lg[0];
        #pragma unroll
        for (int i=1;i<NTAG;i++) m=fmaxf(m,lg[i]);
        float e[NTAG]; float ssum=0.f;
        #pragma unroll
        for (int i=0;i<NTAG;i++){ e[i]=expf(lg[i]-m); ssum+=e[i]; }
        float inv=1.f/ssum;
        float* po=out + ((size_t)b*Sx + s)*NTAG;
        float pr[NTAG];
        #pragma unroll
        for (int i=0;i<NTAG;i++){ pr[i]=e[i]*inv; po[i]=pr[i]; }
        int yc=__ldg(&y[b*Sx+s]);
        float term=pr[yc];
        if (s==0) term += __ldg(&start_t[yc]);
        else      term += __ldg(&trans[__ldg(&y[b*Sx+s-1])*NTAG + yc]);
        if (s==Sx-1) term += __ldg(&end_t[yc]);
        g_sc[b*Sx+s]=term;
    }
}

// ---------------- K3b: CRF forward algorithm + loss ----------------
__global__ void __launch_bounds__(288) k_crf(
        const float* __restrict__ start_t, const float* __restrict__ end_t,
        const float* __restrict__ trans, float* __restrict__ out){
    __shared__ float alpha[Bx][NTAG];
    __shared__ float str[NTAG*NTAG];
    __shared__ float sst[NTAG], sen[NTAG];
    __shared__ float res[Bx];
    const float* probs = out;   // written by k_head
    int t=threadIdx.x;
    if (t<NTAG*NTAG) str[t]=trans[t];
    if (t<NTAG){ sst[t]=start_t[t]; sen[t]=end_t[t]; }
    int b=t/NTAG, j=t-b*NTAG;
    __syncthreads();
    alpha[b][j]=sst[j]+probs[((size_t)b*Sx+0)*NTAG+j];
    __syncthreads();
    float em_next=probs[((size_t)b*Sx+1)*NTAG+j];
    for (int s=1;s<Sx;s++){
        float em=em_next;
        if (s<Sx-1) em_next=probs[((size_t)b*Sx+s+1)*NTAG+j];
        float m=-1e30f; float v[NTAG];
        #pragma unroll
        for (int i=0;i<NTAG;i++){ v[i]=alpha[b][i]+str[i*NTAG+j]; m=fmaxf(m,v[i]); }
        float ssum=0.f;
        #pragma unroll
        for (int i=0;i<NTAG;i++) ssum+=expf(v[i]-m);
        float nxt=m+logf(ssum)+em;
        __syncthreads();
        alpha[b][j]=nxt;
        __syncthreads();
    }
    if (t<Bx){
        int bb=t;
        float m=-1e30f;
        #pragma unroll
        for (int i=0;i<NTAG;i++) m=fmaxf(m,alpha[bb][i]+sen[i]);
        float ssum=0.f;
        #pragma unroll
        for (int i=0;i<NTAG;i++) ssum+=expf(alpha[bb][i]+sen[i]-m);
        float denom=m+logf(ssum);
        float sc=0.f;
        for (int s=0;s<Sx;s++) sc+=g_sc[bb*Sx+s];
        res[bb]=sc-denom;
    }
    __syncthreads();
    if (t==0){
        float llh=0.f;
        #pragma unroll
        for (int bb=0;bb<Bx;bb++) llh+=res[bb];
        out[(size_t)Bx*Sx*NTAG]=-llh;
    }
}

// ---------------- launcher ----------------
extern "C" void kernel_launch(void* const* d_in, const int* in_sizes, int n_in,
                              void* d_out, int out_size){
    const int*   x     =(const int*)  d_in[0];
    const int*   y     =(const int*)  d_in[1];
    const float* emb   =(const float*)d_in[2];
    const float* wihf  =(const float*)d_in[3];
    const float* whhf  =(const float*)d_in[4];
    const float* bihf  =(const float*)d_in[5];
    const float* bhhf  =(const float*)d_in[6];
    const float* wihb  =(const float*)d_in[7];
    const float* whhb  =(const float*)d_in[8];
    const float* bihb  =(const float*)d_in[9];
    const float* bhhb  =(const float*)d_in[10];
    const float* linw  =(const float*)d_in[11];
    const float* linb  =(const float*)d_in[12];
    const float* startt=(const float*)d_in[13];
    const float* endt  =(const float*)d_in[14];
    const float* trans =(const float*)d_in[15];
    float* out=(float*)d_out;
    (void)in_sizes; (void)n_in; (void)out_size;

    static int smem_set = 0;
    if (!smem_set){
        cudaFuncSetAttribute(k_recur, cudaFuncAttributeMaxDynamicSharedMemorySize, RECUR_SMEM);
        smem_set = 1;
    }

    k_embed<<<(Bx*Sx*EMBD+255)/256,256>>>(x, emb);
    dim3 gg(8192/128, (NCOL+127)/128);
    k_gx<<<gg,256>>>(wihf, wihb, bihf, bhhf, bihb, bhhb);
    k_recur<<<2*NHS*NBS,256,RECUR_SMEM>>>(whhf, whhb);
    k_head<<<Bx*Sx,288>>>(linw, linb, y, startt, endt, trans, out);
    k_crf<<<1,288>>>(startt, endt, trans, out);
}

// round 3
// speedup vs baseline: 1.1734x; 1.1734x over previous
#include <cuda_runtime.h>
#include <math.h>

#define Bx   32
#define Sx   256
#define EMBD 300
#define HIDD 300
#define NTAG 9
#define GATES 1200          // 4*HIDD
#define NCOL  2400          // both directions

// ---------------- scratch (static device globals; no allocs) ----------------
__device__ float g_E [Bx*Sx*EMBD];            // (S,B,300) gathered embeddings
__device__ float g_gx[19660800];              // (S,B,2400) input-transform + biases
__device__ float g_H [4915200];               // (S,B,600) hidden states (fwd|bwd)
__device__ float g_sc[Bx*Sx];                 // CRF numerator terms
__device__ int   g_ctr[8];                    // recurrence sync counters

__device__ __forceinline__ float fsigm(float x){ return 1.f/(1.f+__expf(-x)); }
__device__ __forceinline__ float ftanh(float x){
    float ax=fabsf(x);
    float t=__expf(-2.f*ax);
    float r=(1.f-t)/(1.f+t);
    return copysignf(r,x);
}

// ---------------- K0: embedding gather + counter reset ----------------
__global__ void k_embed(const int* __restrict__ x, const float* __restrict__ emb){
    if (blockIdx.x==0 && threadIdx.x<8) g_ctr[threadIdx.x]=0;
    int idx = blockIdx.x*blockDim.x + threadIdx.x;
    if (idx < Bx*Sx*EMBD){
        int r = idx/EMBD, k = idx - r*EMBD;
        int s = r/Bx, b = r - s*Bx;
        int tok = __ldg(&x[b*Sx + s]);
        g_E[idx] = __ldg(&emb[(size_t)tok*EMBD + k]);
    }
}

// ---------------- K1: gx GEMM (8192 x 2400 x 300), fp32 tiled ----------------
__global__ void __launch_bounds__(256) k_gx(
        const float* __restrict__ wf, const float* __restrict__ wb,
        const float* __restrict__ bif, const float* __restrict__ bhf,
        const float* __restrict__ bib, const float* __restrict__ bhb){
    __shared__ float As[8][132];
    __shared__ float Bs[8][128];
    int t  = threadIdx.x;
    int m0 = blockIdx.x*128;
    int n0 = blockIdx.y*128;
    int tx = t & 15, ty = t >> 4;

    float acc[8][8];
    #pragma unroll
    for (int i=0;i<8;i++)
        #pragma unroll
        for (int j=0;j<8;j++) acc[i][j]=0.f;

    int arow = t>>1, ahalf = t&1;
    int bn = t>>1,  bh = t&1;
    bool brow_ok = (n0+bn) < NCOL;
    const float* wrp = brow_ok
        ? ((n0+bn) < GATES ? wf + (size_t)(n0+bn)*EMBD
                           : wb + (size_t)(n0+bn-GATES)*EMBD)
        : wf;

    float4 aR, bRv;
    {   // prefetch chunk 0 (k = 0..7; bh*4 < EMBD always)
        aR  = *(const float4*)(g_E + (size_t)(m0+arow)*EMBD + ahalf*4);
        bRv = brow_ok ? *(const float4*)(wrp + bh*4)
                      : make_float4(0.f,0.f,0.f,0.f);
    }
    for (int ck=0; ck<38; ck++){
        __syncthreads();
        {   float av[4]={aR.x,aR.y,aR.z,aR.w};
            float bv[4]={bRv.x,bRv.y,bRv.z,bRv.w};
            #pragma unroll
            for (int i=0;i<4;i++){ As[ahalf*4+i][arow]=av[i]; Bs[bh*4+i][bn]=bv[i]; }
        }
        __syncthreads();
        if (ck < 37){
            int k0=(ck+1)*8;
            int ka = k0 + ahalf*4;
            int kb = k0 + bh*4;
            aR = (ka<EMBD) ? *(const float4*)(g_E + (size_t)(m0+arow)*EMBD + ka)
                           : make_float4(0.f,0.f,0.f,0.f);
            bRv = (brow_ok && kb<EMBD) ? *(const float4*)(wrp + kb)
                                       : make_float4(0.f,0.f,0.f,0.f);
        }
        #pragma unroll
        for (int kk=0;kk<8;kk++){
            float4 a0=*(const float4*)&As[kk][ty*8];
            float4 a1=*(const float4*)&As[kk][ty*8+4];
            float4 b0=*(const float4*)&Bs[kk][tx*8];
            float4 b1=*(const float4*)&Bs[kk][tx*8+4];
            float av[8]={a0.x,a0.y,a0.z,a0.w,a1.x,a1.y,a1.z,a1.w};
            float bv[8]={b0.x,b0.y,b0.z,b0.w,b1.x,b1.y,b1.z,b1.w};
            #pragma unroll
            for (int i=0;i<8;i++)
                #pragma unroll
                for (int j=0;j<8;j++)
                    acc[i][j]=fmaf(av[i],bv[j],acc[i][j]);
        }
    }
    #pragma unroll
    for (int i=0;i<8;i++){
        int gm = m0 + ty*8 + i;
        #pragma unroll
        for (int j0=0;j0<8;j0+=4){
            int gn = n0 + tx*8 + j0;
            if (gn < NCOL){
                float vv[4];
                #pragma unroll
                for (int j=0;j<4;j++){
                    int c=gn+j;
                    float bias = (c<GATES)? bif[c]+bhf[c] : bib[c-GATES]+bhb[c-GATES];
                    vv[j]=acc[i][j0+j]+bias;
                }
                *(float4*)(g_gx + (size_t)gm*NCOL + gn) =
                    make_float4(vv[0],vv[1],vv[2],vv[3]);
            }
        }
    }
}

// ---------------- K2: persistent bidirectional LSTM recurrence ----------------
#define HS 15          // hidden units per block
#define NHS 20         // hidden slices (20*15=300)
#define NBS 3          // batch slices (11,11,10)
#define NG 60          // 4*HS gate rows per block
#define BMAX 12        // padded per-block batch
#define KSPLIT 5       // k-dim split (5*60=300)
#define RECUR_SMEM ((NG*300 + BMAX*300 + KSPLIT*NG*BMAX + HS*BMAX)*4)

__device__ __forceinline__ void fma4(float& a, float4 w, float4 h){
    a=fmaf(w.x,h.x,a); a=fmaf(w.y,h.y,a); a=fmaf(w.z,h.z,a); a=fmaf(w.w,h.w,a);
}

__device__ __forceinline__ int ld_acquire(const int* p){
    int v;
    asm volatile("ld.acquire.gpu.global.s32 %0, [%1];" : "=r"(v) : "l"(p) : "memory");
    return v;
}
__device__ __forceinline__ void red_release(int* p){
    asm volatile("red.release.gpu.global.add.s32 [%0], %1;" :: "l"(p), "r"(1) : "memory");
}

__global__ void __launch_bounds__(256,1) k_recur(
        const float* __restrict__ whhf, const float* __restrict__ whhb){
    extern __shared__ float smdyn[];
    float* Ws   = smdyn;                       // [NG][300]
    float* Hs   = Ws   + NG*300;               // [BMAX][300]
    float* Part = Hs   + BMAX*300;             // [KSPLIT][NG][BMAX]
    float* Cs   = Part + KSPLIT*NG*BMAX;       // [HS][BMAX]

    int bx  = blockIdx.x;
    int dir = bx / (NHS*NBS);
    int r   = bx % (NHS*NBS);
    int hs  = r / NBS;
    int bs  = r % NBS;
    int bch = (bs<2)?11:10;
    int b0g = bs*11;
    int j0  = hs*HS;
    const float* whh = dir ? whhb : whhf;
    int t = threadIdx.x;

    for (int i=t;i<NG*300;i+=256){
        int row=i/300, k=i-row*300;
        int type=row/HS, jj=row-type*HS;
        Ws[i]=whh[(size_t)(type*HIDD + j0 + jj)*HIDD + k];
    }
    for (int i=t;i<BMAX*300;i+=256) Hs[i]=0.f;
    for (int i=t;i<HS*BMAX;i+=256)  Cs[i]=0.f;
    __syncthreads();

    bool comp=(t<225);
    int kp=0, gt=0, bt=0;
    if (comp){ kp=t/45; int rem=t%45; gt=rem/3; bt=rem%3; }
    int* ctr = g_ctr + dir*NBS + bs;
    bool mycell = (t < HS*bch);
    int cb = t/HS, cj = t - cb*HS;

    for (int step=0; step<Sx; step++){
        int s = dir ? (Sx-1-step) : step;

        // prefetch my gx values (independent of h; hides DRAM latency under spin)
        float pgi=0.f,pgf=0.f,pgg=0.f,pgo=0.f;
        if (mycell){
            const float* gp = g_gx + ((size_t)(s*Bx + b0g + cb))*NCOL + dir*GATES + (j0+cj);
            pgi=gp[0]; pgf=gp[HIDD]; pgg=gp[2*HIDD]; pgo=gp[3*HIDD];
        }

        if (step>0){
            int sprev = dir ? s+1 : s-1;
            int target = NHS*step;
            while (ld_acquire(ctr) < target) { }
            // vectorized H load: 300 floats per batch row = 75 float4
            const float4* hbase = (const float4*)(g_H + (size_t)sprev*Bx*(2*HIDD) + dir*HIDD);
            int n4 = bch*75;
            for (int i=t;i<n4;i+=256){
                int b=i/75, q=i-b*75;
                // row stride 600 floats = 150 float4
                ((float4*)Hs)[b*75+q] = hbase[(size_t)(b0g+b)*150 + q];
            }
        }
        __syncthreads();

        if (comp){
            float acc[4][4];
            #pragma unroll
            for (int i=0;i<4;i++)
                #pragma unroll
                for (int j=0;j<4;j++) acc[i][j]=0.f;
            const float* wr = Ws + (gt*4)*300 + kp*60;
            const float* hr = Hs + (bt*4)*300 + kp*60;
            #pragma unroll
            for (int c=0;c<15;c++){
                int k=c*4;
                float4 w0=*(const float4*)(wr      +k);
                float4 w1=*(const float4*)(wr+300  +k);
                float4 w2=*(const float4*)(wr+600  +k);
                float4 w3=*(const float4*)(wr+900  +k);
                float4 h0=*(const float4*)(hr      +k);
                float4 h1=*(const float4*)(hr+300  +k);
                float4 h2=*(const float4*)(hr+600  +k);
                float4 h3=*(const float4*)(hr+900  +k);
                fma4(acc[0][0],w0,h0); fma4(acc[0][1],w0,h1); fma4(acc[0][2],w0,h2); fma4(acc[0][3],w0,h3);
                fma4(acc[1][0],w1,h0); fma4(acc[1][1],w1,h1); fma4(acc[1][2],w1,h2); fma4(acc[1][3],w1,h3);
                fma4(acc[2][0],w2,h0); fma4(acc[2][1],w2,h1); fma4(acc[2][2],w2,h2); fma4(acc[2][3],w2,h3);
                fma4(acc[3][0],w3,h0); fma4(acc[3][1],w3,h1); fma4(acc[3][2],w3,h2); fma4(acc[3][3],w3,h3);
            }
            #pragma unroll
            for (int i=0;i<4;i++)
                #pragma unroll
                for (int j=0;j<4;j++)
                    Part[(kp*NG + gt*4+i)*BMAX + bt*4+j]=acc[i][j];
        }
        __syncthreads();

        if (mycell){
            float gi=pgi, gf=pgf, gg=pgg, go=pgo;
            #pragma unroll
            for (int kq=0;kq<KSPLIT;kq++){
                gi += Part[(kq*NG + 0*HS+cj)*BMAX + cb];
                gf += Part[(kq*NG + 1*HS+cj)*BMAX + cb];
                gg += Part[(kq*NG + 2*HS+cj)*BMAX + cb];
                go += Part[(kq*NG + 3*HS+cj)*BMAX + cb];
            }
            float co=Cs[cj*BMAX+cb];
            float cn=fsigm(gf)*co + fsigm(gi)*ftanh(gg);
            float hn=fsigm(go)*ftanh(cn);
            Cs[cj*BMAX+cb]=cn;
            g_H[((size_t)(s*Bx + b0g + cb))*(2*HIDD) + dir*HIDD + j0 + cj]=hn;
        }
        __syncthreads();
        if (t==0) red_release(ctr);
    }
}

// ---------------- K3a: logits + softmax + CRF numerator terms ----------------
__global__ void __launch_bounds__(288) k_head(
        const float* __restrict__ linw, const float* __restrict__ linb,
        const int* __restrict__ y, const float* __restrict__ start_t,
        const float* __restrict__ end_t, const float* __restrict__ trans,
        float* __restrict__ out){
    __shared__ float sh[2*HIDD];
    __shared__ float lg[NTAG];
    int bxid=blockIdx.x;
    int b=bxid/Sx, s=bxid%Sx;
    int t=threadIdx.x;
    const float* hrow=g_H + (size_t)(s*Bx+b)*(2*HIDD);
    for (int k=t;k<2*HIDD;k+=288) sh[k]=hrow[k];
    __syncthreads();
    int w=t>>5, lane=t&31;
    float acc=0.f;
    for (int k=lane;k<2*HIDD;k+=32) acc=fmaf(sh[k],__ldg(&linw[w*(2*HIDD)+k]),acc);
    #pragma unroll
    for (int off=16;off;off>>=1) acc += __shfl_down_sync(0xffffffffu,acc,off);
    if (lane==0) lg[w]=acc+__ldg(&linb[w]);
    __syncthreads();
    if (t==0){
        float m=lg[0];
        #pragma unroll
        for (int i=1;i<NTAG;i++) m=fmaxf(m,lg[i]);
        float e[NTAG]; float ssum=0.f;
        #pragma unroll
        for (int i=0;i<NTAG;i++){ e[i]=expf(lg[i]-m); ssum+=e[i]; }
        float inv=1.f/ssum;
        float* po=out + ((size_t)b*Sx + s)*NTAG;
        float pr[NTAG];
        #pragma unroll
        for (int i=0;i<NTAG;i++){ pr[i]=e[i]*inv; po[i]=pr[i]; }
        int yc=__ldg(&y[b*Sx+s]);
        float term=pr[yc];
        if (s==0) term += __ldg(&start_t[yc]);
        else      term += __ldg(&trans[__ldg(&y[b*Sx+s-1])*NTAG + yc]);
        if (s==Sx-1) term += __ldg(&end_t[yc]);
        g_sc[b*Sx+s]=term;
    }
}

// ---------------- K3b: CRF forward algorithm + loss ----------------
__global__ void __launch_bounds__(288) k_crf(
        const float* __restrict__ start_t, const float* __restrict__ end_t,
        const float* __restrict__ trans, float* __restrict__ out){
    __shared__ float alpha[Bx][NTAG];
    __shared__ float str[NTAG*NTAG];
    __shared__ float sst[NTAG], sen[NTAG];
    __shared__ float res[Bx];
    const float* probs = out;   // written by k_head
    int t=threadIdx.x;
    if (t<NTAG*NTAG) str[t]=trans[t];
    if (t<NTAG){ sst[t]=start_t[t]; sen[t]=end_t[t]; }
    int b=t/NTAG, j=t-b*NTAG;
    __syncthreads();
    alpha[b][j]=sst[j]+probs[((size_t)b*Sx+0)*NTAG+j];
    __syncthreads();
    float em_next=probs[((size_t)b*Sx+1)*NTAG+j];
    for (int s=1;s<Sx;s++){
        float em=em_next;
        if (s<Sx-1) em_next=probs[((size_t)b*Sx+s+1)*NTAG+j];
        float m=-1e30f; float v[NTAG];
        #pragma unroll
        for (int i=0;i<NTAG;i++){ v[i]=alpha[b][i]+str[i*NTAG+j]; m=fmaxf(m,v[i]); }
        float ssum=0.f;
        #pragma unroll
        for (int i=0;i<NTAG;i++) ssum+=expf(v[i]-m);
        float nxt=m+logf(ssum)+em;
        __syncthreads();
        alpha[b][j]=nxt;
        __syncthreads();
    }
    if (t<Bx){
        int bb=t;
        float m=-1e30f;
        #pragma unroll
        for (int i=0;i<NTAG;i++) m=fmaxf(m,alpha[bb][i]+sen[i]);
        float ssum=0.f;
        #pragma unroll
        for (int i=0;i<NTAG;i++) ssum+=expf(alpha[bb][i]+sen[i]-m);
        float denom=m+logf(ssum);
        float sc=0.f;
        for (int s=0;s<Sx;s++) sc+=g_sc[bb*Sx+s];
        res[bb]=sc-denom;
    }
    __syncthreads();
    if (t==0){
        float llh=0.f;
        #pragma unroll
        for (int bb=0;bb<Bx;bb++) llh+=res[bb];
        out[(size_t)Bx*Sx*NTAG]=-llh;
    }
}

// ---------------- launcher ----------------
extern "C" void kernel_launch(void* const* d_in, const int* in_sizes, int n_in,
                              void* d_out, int out_size){
    const int*   x     =(const int*)  d_in[0];
    const int*   y     =(const int*)  d_in[1];
    const float* emb   =(const float*)d_in[2];
    const float* wihf  =(const float*)d_in[3];
    const float* whhf  =(const float*)d_in[4];
    const float* bihf  =(const float*)d_in[5];
    const float* bhhf  =(const float*)d_in[6];
    const float* wihb  =(const float*)d_in[7];
    const float* whhb  =(const float*)d_in[8];
    const float* bihb  =(const float*)d_in[9];
    const float* bhhb  =(const float*)d_in[10];
    const float* linw  =(const float*)d_in[11];
    const float* linb  =(const float*)d_in[12];
    const float* startt=(const float*)d_in[13];
    const float* endt  =(const float*)d_in[14];
    const float* trans =(const float*)d_in[15];
    float* out=(float*)d_out;
    (void)in_sizes; (void)n_in; (void)out_size;

    static int smem_set = 0;
    if (!smem_set){
        cudaFuncSetAttribute(k_recur, cudaFuncAttributeMaxDynamicSharedMemorySize, RECUR_SMEM);
        smem_set = 1;
    }

    k_embed<<<(Bx*Sx*EMBD+255)/256,256>>>(x, emb);
    dim3 gg(8192/128, (NCOL+127)/128);
    k_gx<<<gg,256>>>(wihf, wihb, bihf, bhhf, bihb, bhhb);
    k_recur<<<2*NHS*NBS,256,RECUR_SMEM>>>(whhf, whhb);
    k_head<<<Bx*Sx,288>>>(linw, linb, y, startt, endt, trans, out);
    k_crf<<<1,288>>>(startt, endt, trans, out);
}